// round 6
// baseline (speedup 1.0000x reference)
#include <cuda_runtime.h>
#include <math.h>

#define N_NODES 150000
#define D 100
#define T_STEPS 16
#define E_EDGES 262144
#define S_SEEDS 4096
#define K_CAND 9
#define G4 400      // 4*D gates
#define KDIM 200    // concat(x, h_prev)
#define LDP 68      // padded smem stride for GEMM tiles
#define SMEM_GEMM (2 * KDIM * LDP * (int)sizeof(float))

// ---------------- persistent device state (no allocation allowed) ----------
__device__ float g_emb[N_NODES * D];          // node embeddings (60 MB)
__device__ float g_c[N_NODES * D];            // cell state      (60 MB)
__device__ float g_agg[N_NODES * D];          // scatter accumulator (60 MB)
__device__ float g_cnt[N_NODES];              // in-degree counts
__device__ float g_A[S_SEEDS * KDIM];         // [x | h_prev] per seed
__device__ float g_cprev[S_SEEDS * D];        // c[seed] snapshot
__device__ float g_gates[S_SEEDS * G4];       // LSTM pre-activations
__device__ float g_W[G4 * KDIM];              // [W_ih | W_hh]
__device__ float g_b[G4];                     // b_ih + b_hh
__device__ float g_user[T_STEPS * S_SEEDS * D]; // h_new history (26 MB)

// ---------------- helpers ---------------------------------------------------
__device__ __forceinline__ void red_add_f4(float4* p, float4 v) {
    asm volatile("red.global.add.v4.f32 [%0], {%1,%2,%3,%4};"
                 :: "l"(p), "f"(v.x), "f"(v.y), "f"(v.z), "f"(v.w)
                 : "memory");
}
__device__ __forceinline__ float sigf(float x) {
    return 1.0f / (1.0f + expf(-x));
}

// ---------------- kernels ---------------------------------------------------

// zero the agg buffer (once per launch; update pass re-zeroes it each step)
__global__ void k_zero_agg() {
    int idx = blockIdx.x * blockDim.x + threadIdx.x;
    if (idx < N_NODES * (D / 4)) {
        ((float4*)g_agg)[idx] = make_float4(0.f, 0.f, 0.f, 0.f);
    }
}

// build concatenated W = [W_ih | W_hh] and bias = b_ih + b_hh
__global__ void k_wprep(const float* __restrict__ W_ih,
                        const float* __restrict__ W_hh,
                        const float* __restrict__ b_ih,
                        const float* __restrict__ b_hh) {
    int idx = blockIdx.x * blockDim.x + threadIdx.x;
    if (idx < G4 * KDIM) {
        int g = idx / KDIM, k = idx - g * KDIM;
        g_W[idx] = (k < D) ? W_ih[g * D + k] : W_hh[g * D + (k - D)];
    }
    if (idx < G4) g_b[idx] = b_ih[idx] + b_hh[idx];
}

// per step, BEFORE aggregation: snapshot h_prev (into g_A[:,100:200]) and
// c_prev; also zero the count buffer for this step's edges.
__global__ void k_prep(const int* __restrict__ seeds) {
    int idx = blockIdx.x * blockDim.x + threadIdx.x;
    if (idx < S_SEEDS * (D / 4)) {
        int s = idx / (D / 4), q = idx - s * (D / 4);
        int node = seeds[s];
        const float4* er = (const float4*)(g_emb + (long long)node * D);
        const float4* cr = (const float4*)(g_c + (long long)node * D);
        ((float4*)g_A)[s * (KDIM / 4) + (D / 4) + q] = er[q];  // h_prev half
        ((float4*)g_cprev)[idx] = cr[q];
    }
    if (idx < N_NODES) g_cnt[idx] = 0.0f;
}

// edge scatter: one warp per edge; lanes 0..24 each own one float4 of the row.
__global__ void k_edges(const int* __restrict__ src,
                        const int* __restrict__ dst,
                        const int* __restrict__ cat,
                        const float* __restrict__ rel) {
    int e = blockIdx.x * 8 + (threadIdx.x >> 5);
    if (e >= E_EDGES) return;
    int lane = threadIdx.x & 31;
    int s = src[e];
    int d = dst[e];
    int c = cat[e];
    if (lane < D / 4) {
        float4 a = ((const float4*)(g_emb + (long long)s * D))[lane];
        float4 r = ((const float4*)(rel + (long long)c * D))[lane];
        float4 m = make_float4(a.x * r.x, a.y * r.y, a.z * r.z, a.w * r.w);
        red_add_f4(((float4*)(g_agg + (long long)d * D)) + lane, m);
    }
    if (lane == D / 4) atomicAdd(&g_cnt[d], 1.0f);
}

// emb += agg / max(cnt,1); re-zero agg for next step.
__global__ void k_update() {
    int idx = blockIdx.x * blockDim.x + threadIdx.x;
    if (idx >= N_NODES * (D / 4)) return;
    int n = idx / (D / 4);
    float r = 1.0f / fmaxf(g_cnt[n], 1.0f);
    float4 a = ((float4*)g_agg)[idx];
    float4 e = ((float4*)g_emb)[idx];
    e.x += a.x * r; e.y += a.y * r; e.z += a.z * r; e.w += a.w * r;
    ((float4*)g_emb)[idx] = e;
    ((float4*)g_agg)[idx] = make_float4(0.f, 0.f, 0.f, 0.f);
}

// gather x = emb[seed] (post-aggregation) into g_A[:,0:100]
__global__ void k_gather_x(const int* __restrict__ seeds) {
    int idx = blockIdx.x * blockDim.x + threadIdx.x;
    if (idx >= S_SEEDS * (D / 4)) return;
    int s = idx / (D / 4), q = idx - s * (D / 4);
    int node = seeds[s];
    ((float4*)g_A)[s * (KDIM / 4) + q] =
        ((const float4*)(g_emb + (long long)node * D))[q];
}

// gates = A @ W^T + b : M=4096, N=400, K=200 fp32 SIMT GEMM.
// 64x64 block tile, 4x4 per-thread microtile, full-K smem-resident (transposed).
__global__ void __launch_bounds__(256) k_gemm() {
    extern __shared__ float sm[];
    float* As = sm;                 // [KDIM][LDP]
    float* Bs = sm + KDIM * LDP;    // [KDIM][LDP]
    int tid = threadIdx.x;
    int tx = tid & 15, ty = tid >> 4;
    int s0 = blockIdx.x * 64;
    int g0 = blockIdx.y * 64;

    for (int i = tid; i < 64 * KDIM; i += 256) {
        int r = i / KDIM, k = i - r * KDIM;
        As[k * LDP + r] = g_A[(s0 + r) * KDIM + k];
    }
    for (int i = tid; i < 64 * KDIM; i += 256) {
        int r = i / KDIM, k = i - r * KDIM;
        int g = g0 + r;
        Bs[k * LDP + r] = (g < G4) ? g_W[g * KDIM + k] : 0.0f;
    }
    __syncthreads();

    float acc[4][4];
#pragma unroll
    for (int i = 0; i < 4; i++)
#pragma unroll
        for (int j = 0; j < 4; j++) acc[i][j] = 0.0f;

#pragma unroll 8
    for (int k = 0; k < KDIM; k++) {
        float4 a = *(const float4*)(As + k * LDP + ty * 4);
        float4 b = *(const float4*)(Bs + k * LDP + tx * 4);
        float av[4] = {a.x, a.y, a.z, a.w};
        float bv[4] = {b.x, b.y, b.z, b.w};
#pragma unroll
        for (int i = 0; i < 4; i++)
#pragma unroll
            for (int j = 0; j < 4; j++) acc[i][j] += av[i] * bv[j];
    }

#pragma unroll
    for (int i = 0; i < 4; i++) {
        int srow = s0 + ty * 4 + i;
#pragma unroll
        for (int j = 0; j < 4; j++) {
            int g = g0 + tx * 4 + j;
            if (g < G4) g_gates[srow * G4 + g] = acc[i][j] + g_b[g];
        }
    }
}

// LSTM pointwise; writes h back into emb[seed], c[seed], and the user history.
__global__ void k_point(const int* __restrict__ seeds, int t) {
    int s = blockIdx.x;
    int j = threadIdx.x;
    if (j >= D) return;
    const float* gr = g_gates + s * G4;
    float ig = gr[j];
    float fg = gr[D + j];
    float gg = gr[2 * D + j];
    float og = gr[3 * D + j];
    float cp = g_cprev[s * D + j];
    float cn = sigf(fg) * cp + sigf(ig) * tanhf(gg);
    float hn = sigf(og) * tanhf(cn);
    long long node = seeds[s];
    g_emb[node * D + j] = hn;
    g_c[node * D + j] = cn;
    g_user[((long long)t * S_SEEDS + s) * D + j] = hn;
}

// scores[n][k] = dot(user[n], emb[cand[n][k]])
__global__ void k_score(const int* __restrict__ cand,
                        float* __restrict__ out) {
    __shared__ float u[D];
    int n = blockIdx.x;
    int tid = threadIdx.x;
    if (tid < D) u[tid] = g_user[(long long)n * D + tid];
    __syncthreads();
    int w = tid >> 5, lane = tid & 31;
    for (int k = w; k < K_CAND; k += 8) {
        int cidx = cand[(long long)n * K_CAND + k];
        const float* cr = g_emb + (long long)cidx * D;
        float sum = 0.0f;
        for (int j = lane; j < D; j += 32) sum += u[j] * cr[j];
#pragma unroll
        for (int o = 16; o; o >>= 1) sum += __shfl_down_sync(0xffffffffu, sum, o);
        if (lane == 0) out[(long long)n * K_CAND + k] = sum;
    }
}

// ---------------- host ------------------------------------------------------
extern "C" void kernel_launch(void* const* d_in, const int* in_sizes, int n_in,
                              void* d_out, int out_size) {
    const float* node_emb = (const float*)d_in[0];
    const float* cx       = (const float*)d_in[1];
    const float* rel      = (const float*)d_in[2];
    const float* W_ih     = (const float*)d_in[3];
    const float* W_hh     = (const float*)d_in[4];
    const float* b_ih     = (const float*)d_in[5];
    const float* b_hh     = (const float*)d_in[6];
    const int* src   = (const int*)d_in[7];    // JAX x64-disabled: int32
    const int* dst   = (const int*)d_in[8];
    const int* cat   = (const int*)d_in[9];
    const int* seeds = (const int*)d_in[10];
    const int* cand  = (const int*)d_in[11];
    float* out = (float*)d_out;

    (void)in_sizes; (void)n_in; (void)out_size;

    cudaFuncSetAttribute(k_gemm, cudaFuncAttributeMaxDynamicSharedMemorySize,
                         SMEM_GEMM);

    // reset state from inputs every call (graph-replay deterministic)
    cudaMemcpyToSymbolAsync(g_emb, node_emb, sizeof(float) * N_NODES * D, 0,
                            cudaMemcpyDeviceToDevice, 0);
    cudaMemcpyToSymbolAsync(g_c, cx, sizeof(float) * N_NODES * D, 0,
                            cudaMemcpyDeviceToDevice, 0);

    int nd4 = N_NODES * (D / 4);
    k_zero_agg<<<(nd4 + 255) / 256, 256>>>();
    k_wprep<<<(G4 * KDIM + 255) / 256, 256>>>(W_ih, W_hh, b_ih, b_hh);

    int prep_threads = (N_NODES > S_SEEDS * (D / 4)) ? N_NODES
                                                     : S_SEEDS * (D / 4);
    for (int t = 0; t < T_STEPS; t++) {
        const int* seeds_t = seeds + (long long)t * S_SEEDS;
        k_prep<<<(prep_threads + 255) / 256, 256>>>(seeds_t);
        k_edges<<<E_EDGES / 8, 256>>>(src + (long long)t * E_EDGES,
                                      dst + (long long)t * E_EDGES,
                                      cat + (long long)t * E_EDGES, rel);
        k_update<<<(nd4 + 255) / 256, 256>>>();
        k_gather_x<<<(S_SEEDS * (D / 4) + 255) / 256, 256>>>(seeds_t);
        k_gemm<<<dim3(S_SEEDS / 64, (G4 + 63) / 64), 256, SMEM_GEMM>>>();
        k_point<<<S_SEEDS, 128>>>(seeds_t, t);
    }

    k_score<<<T_STEPS * S_SEEDS, 256>>>(cand, out);
}